// round 3
// baseline (speedup 1.0000x reference)
#include <cuda_runtime.h>
#include <math.h>

#define BATCH 4
#define SEQ 2048
#define DM 512
#define NH 8
#define HD 64
#define ROWS (BATCH*SEQ)
#define RPE_LEN (2*SEQ-1)

// Scratch (static __device__ — no allocations allowed)
__device__ float g_q[BATCH*NH*SEQ*HD];     // (b,h,s,d) 16MB
__device__ float g_k[BATCH*NH*SEQ*HD];
__device__ float g_v[BATCH*NH*SEQ*HD];
__device__ float g_o[BATCH*SEQ*DM];        // concat-head attention output
__device__ float g_sig[NH*RPE_LEN];        // sigmoid(rpe) per head
__device__ float g_scale[NH];              // exp(min(logit_scale, ln 100))

// ---------------------------------------------------------------------------
// Kernel 1: precompute sigmoid(rpe) table (head-major) and per-head scale
// ---------------------------------------------------------------------------
__global__ void prep_kernel(const float* __restrict__ rpe,
                            const float* __restrict__ ls) {
    int i = blockIdx.x * blockDim.x + threadIdx.x;
    if (i < NH * RPE_LEN) {
        int hh = i % NH;
        int p  = i / NH;
        float x = rpe[p * NH + hh];
        g_sig[hh * RPE_LEN + p] = 1.0f / (1.0f + __expf(-x));
    }
    if (i < NH) {
        g_scale[i] = __expf(fminf(ls[i], 4.6051701859880914f)); // ln(100)
    }
}

// ---------------------------------------------------------------------------
// Kernel 2: fused QKV projection.
// q[b,h,s,d] = sum_c query[b,s,c] * W[d*NH + h, c] + bias[d*NH + h]
// grid = (ROWS/64, NH, 3), block = 256, 64x64 tile, 4x4 per-thread micro.
// ---------------------------------------------------------------------------
__global__ __launch_bounds__(256) void qkv_kernel(
    const float* __restrict__ X,
    const float* __restrict__ Wq, const float* __restrict__ bq,
    const float* __restrict__ Wk, const float* __restrict__ bk,
    const float* __restrict__ Wv, const float* __restrict__ bv) {
    const int h     = blockIdx.y;
    const int which = blockIdx.z;
    const float* W    = (which == 0) ? Wq : (which == 1) ? Wk : Wv;
    const float* bias = (which == 0) ? bq : (which == 1) ? bk : bv;
    float* out        = (which == 0) ? g_q : (which == 1) ? g_k : g_v;

    const int row0 = blockIdx.x * 64;
    __shared__ float As[16][68];   // [k][m]
    __shared__ float Bs[16][68];   // [k][n]  (n = head-dim index d)

    const int tid = threadIdx.x;
    const int tx = tid & 15, ty = tid >> 4;
    const int lm = tid >> 2;          // 0..63
    const int lk = (tid & 3) * 4;     // 0,4,8,12

    float acc[4][4] = {};

    for (int k0 = 0; k0 < DM; k0 += 16) {
        float4 a = *(const float4*)(X + (row0 + lm) * DM + k0 + lk);
        As[lk + 0][lm] = a.x; As[lk + 1][lm] = a.y;
        As[lk + 2][lm] = a.z; As[lk + 3][lm] = a.w;
        float4 w4 = *(const float4*)(W + (lm * NH + h) * DM + k0 + lk);
        Bs[lk + 0][lm] = w4.x; Bs[lk + 1][lm] = w4.y;
        Bs[lk + 2][lm] = w4.z; Bs[lk + 3][lm] = w4.w;
        __syncthreads();
#pragma unroll
        for (int k = 0; k < 16; k++) {
            float4 av  = *(float4*)&As[k][ty * 4];
            float4 bv4 = *(float4*)&Bs[k][tx * 4];
            float aa[4] = {av.x, av.y, av.z, av.w};
            float bb[4] = {bv4.x, bv4.y, bv4.z, bv4.w};
#pragma unroll
            for (int i = 0; i < 4; i++)
#pragma unroll
                for (int j = 0; j < 4; j++)
                    acc[i][j] += aa[i] * bb[j];
        }
        __syncthreads();
    }

#pragma unroll
    for (int i = 0; i < 4; i++) {
        int r = row0 + ty * 4 + i;
        int b = r >> 11;            // /SEQ
        int s = r & (SEQ - 1);
        float4 o;
        o.x = acc[i][0] + bias[(tx * 4 + 0) * NH + h];
        o.y = acc[i][1] + bias[(tx * 4 + 1) * NH + h];
        o.z = acc[i][2] + bias[(tx * 4 + 2) * NH + h];
        o.w = acc[i][3] + bias[(tx * 4 + 3) * NH + h];
        *(float4*)(out + ((b * NH + h) * SEQ + s) * HD + tx * 4) = o;
    }
}

// ---------------------------------------------------------------------------
// Kernel 3: flash attention per (b,h). grid = (SEQ/64, BATCH*NH), block 256.
// Dynamic smem: Qt[64][68] (d-major), Kt[64][68] (d-major), Vs[64][68],
// Ps[64][68], sg[128]
// ---------------------------------------------------------------------------
#define ATTN_SMEM_FLOATS (4 * 64 * 68 + 128)
#define ATTN_SMEM_BYTES  (ATTN_SMEM_FLOATS * 4)

__global__ __launch_bounds__(256) void attn_kernel() {
    extern __shared__ float sm[];
    float* Qt = sm;                    // [d][row]
    float* Kt = sm + 1 * 64 * 68;      // [d][key]
    float* Vs = sm + 2 * 64 * 68;      // [key][d]
    float* Ps = sm + 3 * 64 * 68;      // [row][key]
    float* sg = sm + 4 * 64 * 68;      // [127]

    const int bh = blockIdx.y;
    const int b = bh >> 3, h = bh & 7;
    const float* Q = g_q + (size_t)bh * SEQ * HD;
    const float* K = g_k + (size_t)bh * SEQ * HD;
    const float* V = g_v + (size_t)bh * SEQ * HD;
    const int q0 = blockIdx.x * 64;

    const int tid = threadIdx.x;
    const int tx = tid & 15, ty = tid >> 4;
    const float cscale = g_scale[h] * 0.04419417382415922f;  // 1/sqrt(512)

    // Load Q tile transposed (d-major)
    for (int e = tid; e < 1024; e += 256) {
        int row = e >> 4;
        int dd  = (e & 15) * 4;
        float4 qv = *(const float4*)(Q + (q0 + row) * HD + dd);
        Qt[(dd + 0) * 68 + row] = qv.x;
        Qt[(dd + 1) * 68 + row] = qv.y;
        Qt[(dd + 2) * 68 + row] = qv.z;
        Qt[(dd + 3) * 68 + row] = qv.w;
    }

    float m[4], l[4], O[4][4];
#pragma unroll
    for (int i = 0; i < 4; i++) {
        m[i] = -1e30f; l[i] = 0.0f;
#pragma unroll
        for (int j = 0; j < 4; j++) O[i][j] = 0.0f;
    }

    for (int kt = 0; kt < 32; kt++) {
        const int k0 = kt * 64;
        // Load K (transposed) and V tiles
        for (int e = tid; e < 1024; e += 256) {
            int row = e >> 4;
            int dd  = (e & 15) * 4;
            float4 kv = *(const float4*)(K + (k0 + row) * HD + dd);
            Kt[(dd + 0) * 68 + row] = kv.x;
            Kt[(dd + 1) * 68 + row] = kv.y;
            Kt[(dd + 2) * 68 + row] = kv.z;
            Kt[(dd + 3) * 68 + row] = kv.w;
            float4 vv = *(const float4*)(V + (k0 + row) * HD + dd);
            *(float4*)&Vs[row * 68 + dd] = vv;
        }
        // RPE bias slice: idx = (q0+rq) - (k0+rk) + 2047 -> base + (rq-rk+63)
        for (int t = tid; t < 127; t += 256)
            sg[t] = g_sig[h * RPE_LEN + (q0 - k0 + 1984) + t];
        __syncthreads();

        // S = Q K^T  (4x4 per-thread micro over d)
        float sacc[4][4] = {};
#pragma unroll 8
        for (int d = 0; d < 64; d++) {
            float4 qv = *(float4*)&Qt[d * 68 + ty * 4];
            float4 kv = *(float4*)&Kt[d * 68 + tx * 4];
            float qq[4] = {qv.x, qv.y, qv.z, qv.w};
            float kk[4] = {kv.x, kv.y, kv.z, kv.w};
#pragma unroll
            for (int i = 0; i < 4; i++)
#pragma unroll
                for (int j = 0; j < 4; j++)
                    sacc[i][j] += qq[i] * kk[j];
        }

        // scale + bias, online softmax update (reduce across 16 tx lanes)
#pragma unroll
        for (int i = 0; i < 4; i++) {
            float pv[4];
            float rmax = -1e30f;
#pragma unroll
            for (int j = 0; j < 4; j++) {
                float sv = sacc[i][j] * cscale +
                           sg[(ty * 4 + i) - (tx * 4 + j) + 63];
                pv[j] = sv;
                rmax = fmaxf(rmax, sv);
            }
#pragma unroll
            for (int off = 8; off; off >>= 1)
                rmax = fmaxf(rmax, __shfl_xor_sync(0xffffffffu, rmax, off));
            float mnew  = fmaxf(m[i], rmax);
            float alpha = __expf(m[i] - mnew);
            float rsum = 0.0f;
#pragma unroll
            for (int j = 0; j < 4; j++) {
                pv[j] = __expf(pv[j] - mnew);
                rsum += pv[j];
            }
#pragma unroll
            for (int off = 8; off; off >>= 1)
                rsum += __shfl_xor_sync(0xffffffffu, rsum, off);
            l[i] = l[i] * alpha + rsum;
            m[i] = mnew;
#pragma unroll
            for (int j = 0; j < 4; j++) O[i][j] *= alpha;
            *(float4*)&Ps[(ty * 4 + i) * 68 + tx * 4] =
                make_float4(pv[0], pv[1], pv[2], pv[3]);
        }
        __syncthreads();

        // O += P V
#pragma unroll 8
        for (int k = 0; k < 64; k++) {
            float4 vv = *(float4*)&Vs[k * 68 + tx * 4];
#pragma unroll
            for (int i = 0; i < 4; i++) {
                float pp = Ps[(ty * 4 + i) * 68 + k];
                O[i][0] += pp * vv.x;
                O[i][1] += pp * vv.y;
                O[i][2] += pp * vv.z;
                O[i][3] += pp * vv.w;
            }
        }
        __syncthreads();
    }

    // Normalize and write to concat-head layout: col = h*64 + d
#pragma unroll
    for (int i = 0; i < 4; i++) {
        float inv = 1.0f / l[i];
        int s = q0 + ty * 4 + i;
        float4 o = make_float4(O[i][0] * inv, O[i][1] * inv,
                               O[i][2] * inv, O[i][3] * inv);
        *(float4*)(g_o + ((size_t)(b * SEQ + s)) * DM + h * HD + tx * 4) = o;
    }
}

// ---------------------------------------------------------------------------
// Kernel 4: output projection. out[r,j] = sum_c g_o[r,c]*Wp[j,c] + bp[j]
// grid = (ROWS/64, DM/64), block 256.
// ---------------------------------------------------------------------------
__global__ __launch_bounds__(256) void oproj_kernel(
    const float* __restrict__ Wp, const float* __restrict__ bp,
    float* __restrict__ out) {
    const int row0 = blockIdx.x * 64;
    const int n0   = blockIdx.y * 64;
    __shared__ float As[16][68];
    __shared__ float Bs[16][68];

    const int tid = threadIdx.x;
    const int tx = tid & 15, ty = tid >> 4;
    const int lm = tid >> 2;
    const int lk = (tid & 3) * 4;

    float acc[4][4] = {};

    for (int k0 = 0; k0 < DM; k0 += 16) {
        float4 a = *(const float4*)(g_o + (row0 + lm) * DM + k0 + lk);
        As[lk + 0][lm] = a.x; As[lk + 1][lm] = a.y;
        As[lk + 2][lm] = a.z; As[lk + 3][lm] = a.w;
        float4 w4 = *(const float4*)(Wp + (n0 + lm) * DM + k0 + lk);
        Bs[lk + 0][lm] = w4.x; Bs[lk + 1][lm] = w4.y;
        Bs[lk + 2][lm] = w4.z; Bs[lk + 3][lm] = w4.w;
        __syncthreads();
#pragma unroll
        for (int k = 0; k < 16; k++) {
            float4 av  = *(float4*)&As[k][ty * 4];
            float4 bv4 = *(float4*)&Bs[k][tx * 4];
            float aa[4] = {av.x, av.y, av.z, av.w};
            float bb[4] = {bv4.x, bv4.y, bv4.z, bv4.w};
#pragma unroll
            for (int i = 0; i < 4; i++)
#pragma unroll
                for (int j = 0; j < 4; j++)
                    acc[i][j] += aa[i] * bb[j];
        }
        __syncthreads();
    }

#pragma unroll
    for (int i = 0; i < 4; i++) {
        int r = row0 + ty * 4 + i;
        float4 o;
        o.x = acc[i][0] + bp[n0 + tx * 4 + 0];
        o.y = acc[i][1] + bp[n0 + tx * 4 + 1];
        o.z = acc[i][2] + bp[n0 + tx * 4 + 2];
        o.w = acc[i][3] + bp[n0 + tx * 4 + 3];
        *(float4*)(out + r * DM + n0 + tx * 4) = o;
    }
}

// ---------------------------------------------------------------------------
extern "C" void kernel_launch(void* const* d_in, const int* in_sizes, int n_in,
                              void* d_out, int out_size) {
    (void)in_sizes; (void)n_in; (void)out_size;
    const float* query = (const float*)d_in[0];
    const float* Wq = (const float*)d_in[1];
    const float* bq = (const float*)d_in[2];
    const float* Wk = (const float*)d_in[3];
    const float* bk = (const float*)d_in[4];
    const float* Wv = (const float*)d_in[5];
    const float* bv = (const float*)d_in[6];
    const float* Wp = (const float*)d_in[7];
    const float* bp = (const float*)d_in[8];
    const float* ls = (const float*)d_in[9];
    const float* rpe = (const float*)d_in[10];

    cudaFuncSetAttribute(attn_kernel,
                         cudaFuncAttributeMaxDynamicSharedMemorySize,
                         ATTN_SMEM_BYTES);

    prep_kernel<<<(NH * RPE_LEN + 255) / 256, 256>>>(rpe, ls);
    qkv_kernel<<<dim3(ROWS / 64, NH, 3), 256>>>(query, Wq, bq, Wk, bk, Wv, bv);
    attn_kernel<<<dim3(SEQ / 64, BATCH * NH), 256, ATTN_SMEM_BYTES>>>();
    oproj_kernel<<<dim3(ROWS / 64, DM / 64), 256>>>(Wp, bp, (float*)d_out);
}

// round 11
// speedup vs baseline: 2.1027x; 2.1027x over previous
#include <cuda_runtime.h>
#include <cuda_bf16.h>
#include <math.h>
#include <stdint.h>

#define BATCH 4
#define SEQ 2048
#define DM 512
#define NH 8
#define HD 64
#define ROWS (BATCH*SEQ)
#define RPE_LEN (2*SEQ-1)

// Scratch (static __device__ — no allocations allowed)
__device__ float g_q[BATCH*NH*SEQ*HD];
__device__ float g_k[BATCH*NH*SEQ*HD];
__device__ float g_v[BATCH*NH*SEQ*HD];
__device__ float g_o[BATCH*SEQ*DM];
__device__ float g_sig[NH*RPE_LEN];
__device__ float g_scale[NH];

// ===========================================================================
// mma.sync bf16 helpers (compute_103-safe: sm_80+ instructions only)
// ===========================================================================
__device__ __forceinline__ void mma_bf16(float d[4], const uint32_t a[4],
                                         const uint32_t b[2]) {
    asm volatile(
        "mma.sync.aligned.m16n8k16.row.col.f32.bf16.bf16.f32 "
        "{%0,%1,%2,%3}, {%4,%5,%6,%7}, {%8,%9}, {%0,%1,%2,%3};"
        : "+f"(d[0]), "+f"(d[1]), "+f"(d[2]), "+f"(d[3])
        : "r"(a[0]), "r"(a[1]), "r"(a[2]), "r"(a[3]), "r"(b[0]), "r"(b[1]));
}

// pack two f32 into bf16x2 (x0 -> low half, x1 -> high half)
__device__ __forceinline__ uint32_t pack2bf(float x0, float x1) {
    uint32_t r;
    asm("cvt.rn.bf16x2.f32 %0, %1, %2;" : "=r"(r) : "f"(x1), "f"(x0));
    return r;
}

// split (x0,x1) into hi bf16x2 + residual-lo bf16x2
__device__ __forceinline__ void split2(float x0, float x1,
                                       uint32_t& hp, uint32_t& lp) {
    hp = pack2bf(x0, x1);
    float h0 = __uint_as_float(hp << 16);
    float h1 = __uint_as_float(hp & 0xFFFF0000u);
    lp = pack2bf(x0 - h0, x1 - h1);
}

#define LDT 72          // bf16 tile row stride (64 + 8 pad): conflict-free frags
#define CS_LD 130       // f32 epilogue staging stride

// GEMM smem layout (bytes)
#define OF_BIAS 0
#define OF_T    512
#define T_A_HI  (OF_T)
#define T_A_LO  (OF_T + 18432)
#define T_B_HI  (OF_T + 36864)
#define T_B_LO  (OF_T + 55296)
#define GEMM_SMEM_BYTES (512 + 4*18432)      // 74240; Cs (66560) aliases tiles

// ---------------------------------------------------------------------------
// Kernel 1: precompute sigmoid(rpe) + per-head scale
// ---------------------------------------------------------------------------
__global__ void prep_kernel(const float* __restrict__ rpe,
                            const float* __restrict__ ls) {
    int i = blockIdx.x * blockDim.x + threadIdx.x;
    if (i < NH * RPE_LEN) {
        int hh = i % NH;
        int p  = i / NH;
        float x = rpe[p * NH + hh];
        g_sig[hh * RPE_LEN + p] = 1.0f / (1.0f + __expf(-x));
    }
    if (i < NH) g_scale[i] = __expf(fminf(ls[i], 4.6051701859880914f));
}

// ---------------------------------------------------------------------------
// Shared 128x128 GEMM tile via mma.sync, split-bf16 fp32 emulation.
// C = A(128 x 512) * B(128 rows x 512)^T, both fp32 row-major ld=512.
// Result staged into Cs[col*CS_LD + row] (Cs aliases tile smem).
// 256 threads = 8 warps in 2(m) x 4(n); warp tile 64x32.
// ---------------------------------------------------------------------------
__device__ __forceinline__ void gemm_tile(const float* __restrict__ A,
                                          const float* __restrict__ B,
                                          char* sm, int tid, float* Cs) {
    const int wid = tid >> 5, lane = tid & 31;
    const int gr = lane >> 2, tg = lane & 3;
    const int wm = (wid >> 2) * 64;
    const int wn = (wid & 3) * 32;

    __nv_bfloat16* Ahi = (__nv_bfloat16*)(sm + T_A_HI);
    __nv_bfloat16* Alo = (__nv_bfloat16*)(sm + T_A_LO);
    __nv_bfloat16* Bhi = (__nv_bfloat16*)(sm + T_B_HI);
    __nv_bfloat16* Blo = (__nv_bfloat16*)(sm + T_B_LO);

    float acc[4][4][4] = {};

    for (int c = 0; c < 8; ++c) {
        const int k0 = c * 64;
        // fp32 -> (hi, lo) bf16 conversion into padded smem tiles
#pragma unroll
        for (int it = 0; it < 16; ++it) {
            int id  = it * 256 + tid;
            int mat = id >> 11;
            int rr  = (id >> 4) & 127;
            int gg  = id & 15;
            const float* src = (mat ? B : A) + (size_t)rr * DM + k0 + gg * 4;
            float4 f = *(const float4*)src;
            uint32_t h0, l0, h1, l1;
            split2(f.x, f.y, h0, l0);
            split2(f.z, f.w, h1, l1);
            int off = rr * LDT + gg * 4;
            *(uint2*)((mat ? Bhi : Ahi) + off) = make_uint2(h0, h1);
            *(uint2*)((mat ? Blo : Alo) + off) = make_uint2(l0, l1);
        }
        __syncthreads();

#pragma unroll
        for (int ks = 0; ks < 4; ++ks) {
            const int cc = ks * 16 + tg * 2;
            uint32_t ahi[4][4], alo[4][4];
#pragma unroll
            for (int mt = 0; mt < 4; ++mt) {
                int r0 = wm + mt * 16 + gr;
                ahi[mt][0] = *(const uint32_t*)(Ahi + r0 * LDT + cc);
                ahi[mt][1] = *(const uint32_t*)(Ahi + (r0 + 8) * LDT + cc);
                ahi[mt][2] = *(const uint32_t*)(Ahi + r0 * LDT + cc + 8);
                ahi[mt][3] = *(const uint32_t*)(Ahi + (r0 + 8) * LDT + cc + 8);
                alo[mt][0] = *(const uint32_t*)(Alo + r0 * LDT + cc);
                alo[mt][1] = *(const uint32_t*)(Alo + (r0 + 8) * LDT + cc);
                alo[mt][2] = *(const uint32_t*)(Alo + r0 * LDT + cc + 8);
                alo[mt][3] = *(const uint32_t*)(Alo + (r0 + 8) * LDT + cc + 8);
            }
#pragma unroll
            for (int nt = 0; nt < 4; ++nt) {
                int n0 = wn + nt * 8 + gr;
                uint32_t bhi[2] = {
                    *(const uint32_t*)(Bhi + n0 * LDT + cc),
                    *(const uint32_t*)(Bhi + n0 * LDT + cc + 8)};
                uint32_t blo[2] = {
                    *(const uint32_t*)(Blo + n0 * LDT + cc),
                    *(const uint32_t*)(Blo + n0 * LDT + cc + 8)};
#pragma unroll
                for (int mt = 0; mt < 4; ++mt) {
                    mma_bf16(acc[mt][nt], ahi[mt], bhi);
                    mma_bf16(acc[mt][nt], ahi[mt], blo);
                    mma_bf16(acc[mt][nt], alo[mt], bhi);
                }
            }
        }
        __syncthreads();
    }

    // stage C into Cs[col][row] (aliases tiles; guarded by the sync above)
#pragma unroll
    for (int mt = 0; mt < 4; ++mt)
#pragma unroll
        for (int nt = 0; nt < 4; ++nt) {
            int r  = wm + mt * 16 + gr;
            int cl = wn + nt * 8 + tg * 2;
            Cs[cl * CS_LD + r]           = acc[mt][nt][0];
            Cs[(cl + 1) * CS_LD + r]     = acc[mt][nt][1];
            Cs[cl * CS_LD + r + 8]       = acc[mt][nt][2];
            Cs[(cl + 1) * CS_LD + r + 8] = acc[mt][nt][3];
        }
    __syncthreads();
}

// ---------------------------------------------------------------------------
// Kernel 2: QKV projections. grid = (64, 4, 3), block 256.
// ---------------------------------------------------------------------------
__global__ __launch_bounds__(256) void qkv_mm_kernel(
    const float* __restrict__ X,
    const float* __restrict__ Wq, const float* __restrict__ bq,
    const float* __restrict__ Wk, const float* __restrict__ bk,
    const float* __restrict__ Wv, const float* __restrict__ bv) {
    extern __shared__ char sm[];
    const int tid = threadIdx.x;
    const int row0 = blockIdx.x * 128;
    const int n0   = blockIdx.y * 128;
    const int which = blockIdx.z;
    const float* W    = (which == 0) ? Wq : (which == 1) ? Wk : Wv;
    const float* bias = (which == 0) ? bq : (which == 1) ? bk : bv;
    float* out        = (which == 0) ? g_q : (which == 1) ? g_k : g_v;

    float* bsm = (float*)(sm + OF_BIAS);
    if (tid < 128) bsm[tid] = bias[n0 + tid];

    float* Cs = (float*)(sm + OF_T);
    gemm_tile(X + (size_t)row0 * DM, W + (size_t)n0 * DM, sm, tid, Cs);

    const int d0base = n0 >> 3;
#pragma unroll
    for (int it = 0; it < 16; ++it) {
        int id  = it * 256 + tid;
        int g   = id & 3;
        int h   = (id >> 2) & 7;
        int row = id >> 5;
        float v[4];
#pragma unroll
        for (int u = 0; u < 4; ++u) {
            int j = h + 32 * g + 8 * u;
            v[u] = Cs[j * CS_LD + row] + bsm[j];
        }
        int r = row0 + row;
        int b = r >> 11;
        int s = r & (SEQ - 1);
        int d0 = d0base + 4 * g;
        *(float4*)(out + ((size_t)((b * NH + h) * SEQ + s)) * HD + d0) =
            make_float4(v[0], v[1], v[2], v[3]);
    }
}

// ---------------------------------------------------------------------------
// Kernel 4: output projection. grid = (64, 4), block 256.
// ---------------------------------------------------------------------------
__global__ __launch_bounds__(256) void oproj_mm_kernel(
    const float* __restrict__ Wp, const float* __restrict__ bp,
    float* __restrict__ out) {
    extern __shared__ char sm[];
    const int tid = threadIdx.x;
    const int row0 = blockIdx.x * 128;
    const int n0   = blockIdx.y * 128;

    float* bsm = (float*)(sm + OF_BIAS);
    if (tid < 128) bsm[tid] = bp[n0 + tid];

    float* Cs = (float*)(sm + OF_T);
    gemm_tile(g_o + (size_t)row0 * DM, Wp + (size_t)n0 * DM, sm, tid, Cs);

#pragma unroll
    for (int it = 0; it < 16; ++it) {
        int id  = it * 256 + tid;
        int q4  = id & 31;
        int row = id >> 5;
        float v[4];
#pragma unroll
        for (int u = 0; u < 4; ++u) {
            int j = 4 * q4 + u;
            v[u] = Cs[j * CS_LD + row] + bsm[j];
        }
        *(float4*)(out + (size_t)(row0 + row) * DM + n0 + 4 * q4) =
            make_float4(v[0], v[1], v[2], v[3]);
    }
}

// ---------------------------------------------------------------------------
// Kernel 3: flash attention via mma.sync. grid = (16, 32), block 256.
// 128 Q-rows per CTA (warp = 16 rows), 64-key tiles, split-bf16 everywhere.
// smem: Khi@0 Klo@9216 Vthi@18432 Vtlo@27648 (each 64*72*2B), sg@36864.
// Q staging reuses bytes [0, 36864).
// ---------------------------------------------------------------------------
#define ALDT 72
#define ATTN_SMEM_BYTES (36864 + 768)

__global__ __launch_bounds__(256) void attn_mm_kernel() {
    extern __shared__ char sm[];
    const int tid = threadIdx.x, wid = tid >> 5, lane = tid & 31;
    const int gr = lane >> 2, tg = lane & 3;
    const int bh = blockIdx.y, b = bh >> 3, h = bh & 7;
    const int q0 = blockIdx.x * 128;
    const float* Q = g_q + (size_t)bh * SEQ * HD;
    const float* K = g_k + (size_t)bh * SEQ * HD;
    const float* V = g_v + (size_t)bh * SEQ * HD;
    const float cscale = g_scale[h] * 0.04419417382415922f;  // 1/sqrt(512)

    // ---- stage Q (fp32 -> split bf16), then lift fragments to registers
    __nv_bfloat16* Qhi = (__nv_bfloat16*)sm;
    __nv_bfloat16* Qlo = (__nv_bfloat16*)(sm + 18432);
#pragma unroll
    for (int it = 0; it < 8; ++it) {
        int id = it * 256 + tid;
        int rr = id >> 4, gg = id & 15;
        float4 f = *(const float4*)(Q + (size_t)(q0 + rr) * HD + gg * 4);
        uint32_t h0, l0, h1, l1;
        split2(f.x, f.y, h0, l0);
        split2(f.z, f.w, h1, l1);
        *(uint2*)(Qhi + rr * ALDT + gg * 4) = make_uint2(h0, h1);
        *(uint2*)(Qlo + rr * ALDT + gg * 4) = make_uint2(l0, l1);
    }
    __syncthreads();

    uint32_t qhi[4][4], qlo[4][4];
    {
        int r0 = wid * 16 + gr;
#pragma unroll
        for (int ks = 0; ks < 4; ++ks) {
            int cc = ks * 16 + tg * 2;
            qhi[ks][0] = *(uint32_t*)(Qhi + r0 * ALDT + cc);
            qhi[ks][1] = *(uint32_t*)(Qhi + (r0 + 8) * ALDT + cc);
            qhi[ks][2] = *(uint32_t*)(Qhi + r0 * ALDT + cc + 8);
            qhi[ks][3] = *(uint32_t*)(Qhi + (r0 + 8) * ALDT + cc + 8);
            qlo[ks][0] = *(uint32_t*)(Qlo + r0 * ALDT + cc);
            qlo[ks][1] = *(uint32_t*)(Qlo + (r0 + 8) * ALDT + cc);
            qlo[ks][2] = *(uint32_t*)(Qlo + r0 * ALDT + cc + 8);
            qlo[ks][3] = *(uint32_t*)(Qlo + (r0 + 8) * ALDT + cc + 8);
        }
    }
    __syncthreads();   // Q staging region is about to be reused for K/V

    __nv_bfloat16* Khi  = (__nv_bfloat16*)sm;
    __nv_bfloat16* Klo  = (__nv_bfloat16*)(sm + 9216);
    __nv_bfloat16* Vthi = (__nv_bfloat16*)(sm + 18432);
    __nv_bfloat16* Vtlo = (__nv_bfloat16*)(sm + 27648);
    float* sg = (float*)(sm + 36864);

    float m0r = -1e30f, m1r = -1e30f, l0r = 0.0f, l1r = 0.0f;
    float Oa[8][4] = {};
    const int qi0 = wid * 16 + gr;   // local q row of c0/c1

    for (int kt = 0; kt < 32; ++kt) {
        const int k0 = kt * 64;
        // ---- convert K [key][d] and V -> Vt [d][key] tiles
#pragma unroll
        for (int it = 0; it < 4; ++it) {
            int id = it * 256 + tid;
            int kk = id >> 4, gg = id & 15;
            float4 f = *(const float4*)(K + (size_t)(k0 + kk) * HD + gg * 4);
            uint32_t h0, l0, h1, l1;
            split2(f.x, f.y, h0, l0);
            split2(f.z, f.w, h1, l1);
            *(uint2*)(Khi + kk * ALDT + gg * 4) = make_uint2(h0, h1);
            *(uint2*)(Klo + kk * ALDT + gg * 4) = make_uint2(l0, l1);
            float4 fv = *(const float4*)(V + (size_t)(k0 + kk) * HD + gg * 4);
            float xs[4] = {fv.x, fv.y, fv.z, fv.w};
#pragma unroll
            for (int u = 0; u < 4; ++u) {
                int d = gg * 4 + u;
                __nv_bfloat16 hb = __float2bfloat16(xs[u]);
                Vthi[d * ALDT + kk] = hb;
                Vtlo[d * ALDT + kk] =
                    __float2bfloat16(xs[u] - __bfloat162float(hb));
            }
        }
        if (tid < 191)
            sg[tid] = g_sig[h * RPE_LEN + (q0 - k0 + 1984) + tid];
        __syncthreads();

        // ---- S = Q K^T (8 n-tiles of 8 keys)
        float p[8][4];
#pragma unroll
        for (int nt = 0; nt < 8; ++nt) {
            p[nt][0] = p[nt][1] = p[nt][2] = p[nt][3] = 0.0f;
            int n0 = nt * 8 + gr;
#pragma unroll
            for (int ks = 0; ks < 4; ++ks) {
                int cc = ks * 16 + tg * 2;
                uint32_t bhi[2] = {*(uint32_t*)(Khi + n0 * ALDT + cc),
                                   *(uint32_t*)(Khi + n0 * ALDT + cc + 8)};
                uint32_t blo[2] = {*(uint32_t*)(Klo + n0 * ALDT + cc),
                                   *(uint32_t*)(Klo + n0 * ALDT + cc + 8)};
                mma_bf16(p[nt], qhi[ks], bhi);
                mma_bf16(p[nt], qhi[ks], blo);
                mma_bf16(p[nt], qlo[ks], bhi);
            }
        }

        // ---- scale + RPE bias + online softmax
        float rmax0 = -1e30f, rmax1 = -1e30f;
#pragma unroll
        for (int nt = 0; nt < 8; ++nt) {
            int kj = nt * 8 + tg * 2;
            p[nt][0] = p[nt][0] * cscale + sg[qi0 - kj + 63];
            p[nt][1] = p[nt][1] * cscale + sg[qi0 - kj + 62];
            p[nt][2] = p[nt][2] * cscale + sg[qi0 - kj + 71];
            p[nt][3] = p[nt][3] * cscale + sg[qi0 - kj + 70];
            rmax0 = fmaxf(rmax0, fmaxf(p[nt][0], p[nt][1]));
            rmax1 = fmaxf(rmax1, fmaxf(p[nt][2], p[nt][3]));
        }
#pragma unroll
        for (int off = 1; off <= 2; off <<= 1) {
            rmax0 = fmaxf(rmax0, __shfl_xor_sync(0xffffffffu, rmax0, off));
            rmax1 = fmaxf(rmax1, __shfl_xor_sync(0xffffffffu, rmax1, off));
        }
        float mn0 = fmaxf(m0r, rmax0), mn1 = fmaxf(m1r, rmax1);
        float al0 = __expf(m0r - mn0), al1 = __expf(m1r - mn1);
        float rs0 = 0.0f, rs1 = 0.0f;
#pragma unroll
        for (int nt = 0; nt < 8; ++nt) {
            p[nt][0] = __expf(p[nt][0] - mn0);
            p[nt][1] = __expf(p[nt][1] - mn0);
            p[nt][2] = __expf(p[nt][2] - mn1);
            p[nt][3] = __expf(p[nt][3] - mn1);
            rs0 += p[nt][0] + p[nt][1];
            rs1 += p[nt][2] + p[nt][3];
        }
#pragma unroll
        for (int off = 1; off <= 2; off <<= 1) {
            rs0 += __shfl_xor_sync(0xffffffffu, rs0, off);
            rs1 += __shfl_xor_sync(0xffffffffu, rs1, off);
        }
        l0r = l0r * al0 + rs0;
        l1r = l1r * al1 + rs1;
        m0r = mn0;
        m1r = mn1;
#pragma unroll
        for (int nt = 0; nt < 8; ++nt) {
            Oa[nt][0] *= al0; Oa[nt][1] *= al0;
            Oa[nt][2] *= al1; Oa[nt][3] *= al1;
        }

        // ---- pack P into A-fragments (register-only, split hi/lo)
        uint32_t phi[4][4], plo[4][4];
#pragma unroll
        for (int ks2 = 0; ks2 < 4; ++ks2) {
            int ntA = 2 * ks2, ntB = 2 * ks2 + 1;
            split2(p[ntA][0], p[ntA][1], phi[ks2][0], plo[ks2][0]);
            split2(p[ntA][2], p[ntA][3], phi[ks2][1], plo[ks2][1]);
            split2(p[ntB][0], p[ntB][1], phi[ks2][2], plo[ks2][2]);
            split2(p[ntB][2], p[ntB][3], phi[ks2][3], plo[ks2][3]);
        }

        // ---- O += P V
#pragma unroll
        for (int nt = 0; nt < 8; ++nt) {
            int n0 = nt * 8 + gr;
#pragma unroll
            for (int ks2 = 0; ks2 < 4; ++ks2) {
                int cc = ks2 * 16 + tg * 2;
                uint32_t vhi[2] = {*(uint32_t*)(Vthi + n0 * ALDT + cc),
                                   *(uint32_t*)(Vthi + n0 * ALDT + cc + 8)};
                uint32_t vlo[2] = {*(uint32_t*)(Vtlo + n0 * ALDT + cc),
                                   *(uint32_t*)(Vtlo + n0 * ALDT + cc + 8)};
                mma_bf16(Oa[nt], phi[ks2], vhi);
                mma_bf16(Oa[nt], phi[ks2], vlo);
                mma_bf16(Oa[nt], plo[ks2], vhi);
            }
        }
        __syncthreads();
    }

    // ---- normalize, write concat-head layout col = h*64 + d
    float inv0 = 1.0f / l0r, inv1 = 1.0f / l1r;
    int qrow = q0 + qi0;
#pragma unroll
    for (int nt = 0; nt < 8; ++nt) {
        int col = h * HD + nt * 8 + tg * 2;
        *(float2*)(g_o + (size_t)(b * SEQ + qrow) * DM + col) =
            make_float2(Oa[nt][0] * inv0, Oa[nt][1] * inv0);
        *(float2*)(g_o + (size_t)(b * SEQ + qrow + 8) * DM + col) =
            make_float2(Oa[nt][2] * inv1, Oa[nt][3] * inv1);
    }
}

// ---------------------------------------------------------------------------
extern "C" void kernel_launch(void* const* d_in, const int* in_sizes, int n_in,
                              void* d_out, int out_size) {
    (void)in_sizes; (void)n_in; (void)out_size;
    const float* query = (const float*)d_in[0];
    const float* Wq = (const float*)d_in[1];
    const float* bq = (const float*)d_in[2];
    const float* Wk = (const float*)d_in[3];
    const float* bk = (const float*)d_in[4];
    const float* Wv = (const float*)d_in[5];
    const float* bv = (const float*)d_in[6];
    const float* Wp = (const float*)d_in[7];
    const float* bp = (const float*)d_in[8];
    const float* ls = (const float*)d_in[9];
    const float* rpe = (const float*)d_in[10];

    cudaFuncSetAttribute(qkv_mm_kernel,
                         cudaFuncAttributeMaxDynamicSharedMemorySize,
                         GEMM_SMEM_BYTES);
    cudaFuncSetAttribute(oproj_mm_kernel,
                         cudaFuncAttributeMaxDynamicSharedMemorySize,
                         GEMM_SMEM_BYTES);
    cudaFuncSetAttribute(attn_mm_kernel,
                         cudaFuncAttributeMaxDynamicSharedMemorySize,
                         ATTN_SMEM_BYTES);

    prep_kernel<<<(NH * RPE_LEN + 255) / 256, 256>>>(rpe, ls);
    qkv_mm_kernel<<<dim3(ROWS / 128, DM / 128, 3), 256, GEMM_SMEM_BYTES>>>(
        query, Wq, bq, Wk, bk, Wv, bv);
    attn_mm_kernel<<<dim3(SEQ / 128, BATCH * NH), 256, ATTN_SMEM_BYTES>>>();
    oproj_mm_kernel<<<dim3(ROWS / 128, DM / 128), 256, GEMM_SMEM_BYTES>>>(
        Wp, bp, (float*)d_out);
}